// round 4
// baseline (speedup 1.0000x reference)
#include <cuda_runtime.h>
#include <math.h>

// ---------------- constants ----------------
#define BATCHN 2
#define SEQL   2048
#define DM     1024
#define DI     2048
#define DS     128
#define NH     32
#define HD     64
#define DPROJ  4384      // 2*DI + 2*DS + NH
#define CONVCH 2304      // DI + 2*DS
#define NC     16        // chunks per sequence
#define CHK    128       // chunk length
#define MTOT   (BATCHN*SEQL)   // 4096

// ---------------- scratch (device globals; no allocation allowed) ----------------
__device__ __align__(16) float g_xn[2][(size_t)MTOT*DM];      // [0]=fwd, [1]=time-flipped
__device__ __align__(16) float g_zx[(size_t)MTOT*DPROJ];
__device__ __align__(16) float g_dt[MTOT*NH];
__device__ __align__(16) float g_acs[BATCHN*NH*NC*CHK];
__device__ __align__(16) float g_conv[(size_t)MTOT*CONVCH];
__device__ __align__(16) float g_states[(size_t)BATCHN*NC*NH*HD*DS];
__device__ __align__(16) float g_prev[(size_t)BATCHN*NC*NH*HD*DS];
__device__ __align__(16) float g_y[(size_t)MTOT*DI];
__device__ __align__(16) float g_yn[(size_t)MTOT*DI];
__device__ __align__(16) float g_ycat[(size_t)MTOT*2*DM];

// ---------------- K0: input rmsnorm (+ flipped copy) ----------------
__global__ void k_rmsnorm_in(const float* __restrict__ x, const float* __restrict__ w) {
    int m = blockIdx.x;
    int t = m & (SEQL - 1);
    const float* xr = x + (size_t)m * DM;
    float v[4];
    float s = 0.f;
#pragma unroll
    for (int i = 0; i < 4; i++) { v[i] = xr[threadIdx.x + i*256]; s += v[i]*v[i]; }
    __shared__ float sh[8];
#pragma unroll
    for (int o = 16; o > 0; o >>= 1) s += __shfl_xor_sync(0xffffffffu, s, o);
    if ((threadIdx.x & 31) == 0) sh[threadIdx.x >> 5] = s;
    __syncthreads();
    if (threadIdx.x < 8) {
        float t2 = sh[threadIdx.x];
#pragma unroll
        for (int o = 4; o > 0; o >>= 1) t2 += __shfl_xor_sync(0xffu, t2, o);
        if (threadIdx.x == 0) sh[0] = t2;
    }
    __syncthreads();
    float inv = rsqrtf(sh[0] * (1.f/DM) + 1e-5f);
    int mf = (m - t) + (SEQL - 1 - t);
#pragma unroll
    for (int i = 0; i < 4; i++) {
        int d = threadIdx.x + i*256;
        float o = v[i] * inv * w[d];
        g_xn[0][(size_t)m *DM + d] = o;
        g_xn[1][(size_t)mf*DM + d] = o;
    }
}

// ---------------- generic SGEMM: C[M,N] = A[M,K] * B[N,K]^T (+bias,+resid,row-flip,col-offset) ----------------
__global__ void __launch_bounds__(256) k_sgemm(
    const float* __restrict__ A, const float* __restrict__ Bm,
    float* __restrict__ C, int N, int K, int ldc, int colOff, int flip,
    const float* __restrict__ bias, const float* __restrict__ resid)
{
    __shared__ __align__(16) float As[16][132];
    __shared__ __align__(16) float Bs[16][132];
    int tid = threadIdx.x;
    int tx = tid & 15, ty = tid >> 4;
    int m0 = blockIdx.y << 7, n0 = blockIdx.x << 7;
    float acc[8][8];
#pragma unroll
    for (int i = 0; i < 8; i++)
#pragma unroll
        for (int j = 0; j < 8; j++) acc[i][j] = 0.f;

    for (int k0 = 0; k0 < K; k0 += 16) {
#pragma unroll
        for (int i = 0; i < 2; i++) {
            int id = tid + i*256;
            int r = id >> 2, cc = (id & 3) << 2;
            float4 va = *(const float4*)(A + (size_t)(m0 + r)*K + k0 + cc);
            As[cc+0][r]=va.x; As[cc+1][r]=va.y; As[cc+2][r]=va.z; As[cc+3][r]=va.w;
            int nr = n0 + r;
            float4 vb = make_float4(0.f,0.f,0.f,0.f);
            if (nr < N) vb = *(const float4*)(Bm + (size_t)nr*K + k0 + cc);
            Bs[cc+0][r]=vb.x; Bs[cc+1][r]=vb.y; Bs[cc+2][r]=vb.z; Bs[cc+3][r]=vb.w;
        }
        __syncthreads();
#pragma unroll
        for (int kk = 0; kk < 16; kk++) {
            float a[8], b[8];
            *(float4*)(a)   = *(const float4*)&As[kk][ty*8];
            *(float4*)(a+4) = *(const float4*)&As[kk][ty*8+4];
            *(float4*)(b)   = *(const float4*)&Bs[kk][tx*8];
            *(float4*)(b+4) = *(const float4*)&Bs[kk][tx*8+4];
#pragma unroll
            for (int i = 0; i < 8; i++)
#pragma unroll
                for (int j = 0; j < 8; j++) acc[i][j] = fmaf(a[i], b[j], acc[i][j]);
        }
        __syncthreads();
    }
#pragma unroll
    for (int i = 0; i < 8; i++) {
        int row = m0 + ty*8 + i;
        int orow = row;
        if (flip) { int t = row & (SEQL-1); orow = (row - t) + (SEQL - 1 - t); }
        float* crow = C + (size_t)orow*ldc + colOff;
#pragma unroll
        for (int j = 0; j < 8; j++) {
            int col = n0 + tx*8 + j;
            if (col < N) {
                float v = acc[i][j];
                if (bias)  v += bias[col];
                if (resid) v += resid[(size_t)row*N + col];
                crow[col] = v;
            }
        }
    }
}

// ---------------- dt (softplus) + per-chunk cumsum of A*dt ----------------
__global__ void k_dtacs(const float* __restrict__ dt_bias, const float* __restrict__ A_log) {
    int bi = blockIdx.x;
    int h = bi & 31, c = (bi >> 5) & 15, b = bi >> 9;
    int l = threadIdx.x;
    int m = b*SEQL + c*CHK + l;
    float raw = g_zx[(size_t)m*DPROJ + (2*DI + 2*DS) + h] + dt_bias[h];
    float dt = fmaxf(raw, 0.f) + log1pf(expf(-fabsf(raw)));  // stable softplus
    g_dt[m*NH + h] = dt;
    float Ah = -expf(A_log[h]);
    __shared__ float sv[CHK];
    float a = Ah * dt;
    sv[l] = a;
    __syncthreads();
#pragma unroll
    for (int off = 1; off < CHK; off <<= 1) {
        float u = (l >= off) ? sv[l - off] : 0.f;
        __syncthreads();
        a += u;
        sv[l] = a;
        __syncthreads();
    }
    g_acs[((b*NH + h)*NC + c)*CHK + l] = a;
}

// ---------------- causal depthwise conv (width 4) + silu ----------------
__global__ void k_conv(const float* __restrict__ cw, const float* __restrict__ cb) {
    int ch = blockIdx.x*256 + threadIdx.x;   // < CONVCH
    int m = blockIdx.y;
    int t = m & (SEQL - 1);
    float acc = cb[ch];
#pragma unroll
    for (int k = 0; k < 4; k++) {
        int tt = t + k - 3;
        if (tt >= 0) acc += g_zx[(size_t)(m + k - 3)*DPROJ + DI + ch] * cw[ch*4 + k];
    }
    float sg = 1.f / (1.f + __expf(-acc));
    g_conv[(size_t)m*CONVCH + ch] = acc * sg;
}

// ---------------- per-chunk states: states[p,n] = sum_l B[l,n]*decay[l]*dt[l]*x[l,p] ----------------
__global__ void __launch_bounds__(256) k_states() {
    int bi = blockIdx.x;
    int h = bi & 31, c = (bi >> 5) & 15, b = bi >> 9;
    __shared__ __align__(16) float Bsh[32][132];
    __shared__ __align__(16) float Xd[32][68];
    int tid = threadIdx.x, tx = tid & 15, ty = tid >> 4;
    const float* acsr = g_acs + ((b*NH + h)*NC + c)*CHK;
    float alast = acsr[CHK - 1];
    int rowBase = b*SEQL + c*CHK;
    float acc[4][8];
#pragma unroll
    for (int i = 0; i < 4; i++)
#pragma unroll
        for (int j = 0; j < 8; j++) acc[i][j] = 0.f;

    for (int lt = 0; lt < CHK; lt += 32) {
#pragma unroll
        for (int i = 0; i < 4; i++) {
            int id = tid + i*256;
            int l = id >> 5, n4 = (id & 31) << 2;
            float4 v = *(const float4*)(g_conv + (size_t)(rowBase + lt + l)*CONVCH + DI + n4);
            *(float4*)&Bsh[l][n4] = v;
        }
#pragma unroll
        for (int i = 0; i < 2; i++) {
            int id = tid + i*256;
            int l = id >> 4, p4 = (id & 15) << 2;
            int row = rowBase + lt + l;
            float4 v = *(const float4*)(g_conv + (size_t)row*CONVCH + h*HD + p4);
            float f = g_dt[row*NH + h] * __expf(alast - acsr[lt + l]);
            v.x *= f; v.y *= f; v.z *= f; v.w *= f;
            *(float4*)&Xd[l][p4] = v;
        }
        __syncthreads();
#pragma unroll 8
        for (int l = 0; l < 32; l++) {
            float a[4], bb[8];
            *(float4*)a      = *(const float4*)&Xd[l][ty*4];
            *(float4*)(bb)   = *(const float4*)&Bsh[l][tx*8];
            *(float4*)(bb+4) = *(const float4*)&Bsh[l][tx*8+4];
#pragma unroll
            for (int i = 0; i < 4; i++)
#pragma unroll
                for (int j = 0; j < 8; j++) acc[i][j] = fmaf(a[i], bb[j], acc[i][j]);
        }
        __syncthreads();
    }
    size_t base = ((size_t)((b*NC + c)*NH + h)) * HD * DS;
#pragma unroll
    for (int i = 0; i < 4; i++) {
        int p = ty*4 + i;
#pragma unroll
        for (int j = 0; j < 8; j += 4) {
            float4 v = make_float4(acc[i][j], acc[i][j+1], acc[i][j+2], acc[i][j+3]);
            *(float4*)(g_states + base + (size_t)p*DS + tx*8 + j) = v;
        }
    }
}

// ---------------- sequential inter-chunk scan ----------------
__global__ void k_scan() {
    int idx = blockIdx.x*256 + threadIdx.x;   // < BATCHN*NH*HD*DS
    int n = idx & 127;
    int p = (idx >> 7) & 63;
    int h = (idx >> 13) & 31;
    int b = idx >> 18;
    const float* acsb = g_acs + ((b*NH + h)*NC)*CHK;
    float s = 0.f;
#pragma unroll
    for (int c = 0; c < NC; c++) {
        size_t off = (((size_t)((b*NC + c)*NH + h))*HD + p)*DS + n;
        g_prev[off] = s;
        s = s * __expf(acsb[c*CHK + CHK - 1]) + g_states[off];
    }
}

// ---------------- per-(b,c,h) Y = diag + off + D-term ----------------
#define YSMEM ((128*132*2 + 128*68 + 256)*4)
__global__ void __launch_bounds__(256) k_y(const float* __restrict__ Dv) {
    extern __shared__ __align__(16) float sm[];
    float* Ct   = sm;                 // C transposed: Ct[n*132 + l]
    float* Gt   = sm + 128*132;       // holds Bt[n*132 + s], then G transposed Gt[s*132 + l]
    float* Xs   = Gt + 128*132;       // raw x: Xs[s*68 + p]; later prev: Pn[n*68 + p]
    float* sAcs = Xs + 128*68;        // 128
    float* sDt  = sAcs + 128;         // 128

    int bi = blockIdx.x;
    int h = bi & 31, c = (bi >> 5) & 15, b = bi >> 9;
    int tid = threadIdx.x, tx = tid & 15, ty = tid >> 4;
    int rowBase = b*SEQL + c*CHK;
    const float* acsr = g_acs + ((b*NH + h)*NC + c)*CHK;
    if (tid < 128) { sAcs[tid] = acsr[tid]; sDt[tid] = g_dt[(rowBase + tid)*NH + h]; }

#pragma unroll
    for (int i = 0; i < 16; i++) {
        int id = tid + i*256;               // 0..4095
        int l = id >> 5, n4 = (id & 31) << 2;
        const float* grow = g_conv + (size_t)(rowBase + l)*CONVCH;
        float4 vc = *(const float4*)(grow + DI + DS + n4);   // C
        Ct[(n4+0)*132 + l] = vc.x; Ct[(n4+1)*132 + l] = vc.y;
        Ct[(n4+2)*132 + l] = vc.z; Ct[(n4+3)*132 + l] = vc.w;
        float4 vb = *(const float4*)(grow + DI + n4);        // B
        Gt[(n4+0)*132 + l] = vb.x; Gt[(n4+1)*132 + l] = vb.y;
        Gt[(n4+2)*132 + l] = vb.z; Gt[(n4+3)*132 + l] = vb.w;
    }
#pragma unroll
    for (int i = 0; i < 8; i++) {
        int id = tid + i*256;               // 0..2047
        int s = id >> 4, p4 = (id & 15) << 2;
        float4 v = *(const float4*)(g_conv + (size_t)(rowBase + s)*CONVCH + h*HD + p4);
        *(float4*)&Xs[s*68 + p4] = v;
    }
    __syncthreads();

    // phase 1: G[l][s] = sum_n C[l,n] * B[s,n]   (l = ty*8+i, s = tx*8+j)
    float g[8][8];
#pragma unroll
    for (int i = 0; i < 8; i++)
#pragma unroll
        for (int j = 0; j < 8; j++) g[i][j] = 0.f;
#pragma unroll 4
    for (int n = 0; n < 128; n++) {
        float a[8], bb[8];
        *(float4*)(a)    = *(const float4*)&Ct[n*132 + ty*8];
        *(float4*)(a+4)  = *(const float4*)&Ct[n*132 + ty*8 + 4];
        *(float4*)(bb)   = *(const float4*)&Gt[n*132 + tx*8];
        *(float4*)(bb+4) = *(const float4*)&Gt[n*132 + tx*8 + 4];
#pragma unroll
        for (int i = 0; i < 8; i++)
#pragma unroll
            for (int j = 0; j < 8; j++) g[i][j] = fmaf(a[i], bb[j], g[i][j]);
    }
    // mask (s<=l) + decay exp(acs[l]-acs[s])
#pragma unroll
    for (int i = 0; i < 8; i++) {
        int l = ty*8 + i; float al = sAcs[l];
#pragma unroll
        for (int j = 0; j < 8; j++) {
            int s = tx*8 + j;
            g[i][j] = (s <= l) ? g[i][j] * __expf(al - sAcs[s]) : 0.f;
        }
    }
    __syncthreads();             // all B reads done -> overwrite with G^T
#pragma unroll
    for (int j = 0; j < 8; j++) {
        float4 v0 = make_float4(g[0][j], g[1][j], g[2][j], g[3][j]);
        float4 v1 = make_float4(g[4][j], g[5][j], g[6][j], g[7][j]);
        *(float4*)&Gt[(tx*8+j)*132 + ty*8]     = v0;
        *(float4*)&Gt[(tx*8+j)*132 + ty*8 + 4] = v1;
    }
    __syncthreads();

    // phase 2: Ydiag[l][p] = sum_s G[l,s] * x[s,p] * dt[s]   (p = tx*4+j)
    float y[8][4];
#pragma unroll
    for (int i = 0; i < 8; i++)
#pragma unroll
        for (int j = 0; j < 4; j++) y[i][j] = 0.f;
#pragma unroll 4
    for (int s = 0; s < 128; s++) {
        float a[8];
        *(float4*)(a)   = *(const float4*)&Gt[s*132 + ty*8];
        *(float4*)(a+4) = *(const float4*)&Gt[s*132 + ty*8 + 4];
        float4 xv = *(const float4*)&Xs[s*68 + tx*4];
        float d = sDt[s];
        float bb[4] = {xv.x*d, xv.y*d, xv.z*d, xv.w*d};
#pragma unroll
        for (int i = 0; i < 8; i++)
#pragma unroll
            for (int j = 0; j < 4; j++) y[i][j] = fmaf(a[i], bb[j], y[i][j]);
    }
    // keep raw x for the D skip-term before Xs gets overwritten
    float xr[8][4];
#pragma unroll
    for (int i = 0; i < 8; i++) {
        float4 v = *(const float4*)&Xs[(ty*8+i)*68 + tx*4];
        xr[i][0]=v.x; xr[i][1]=v.y; xr[i][2]=v.z; xr[i][3]=v.w;
    }
    __syncthreads();
    // load prev-state slice transposed: Pn[n][p]
    size_t pbase = ((size_t)((b*NC + c)*NH + h)) * HD * DS;
#pragma unroll
    for (int i = 0; i < 8; i++) {
        int id = tid + i*256;               // 0..2047
        int p = id >> 5, n4 = (id & 31) << 2;
        float4 v = *(const float4*)(g_prev + pbase + (size_t)p*DS + n4);
        Xs[(n4+0)*68 + p] = v.x; Xs[(n4+1)*68 + p] = v.y;
        Xs[(n4+2)*68 + p] = v.z; Xs[(n4+3)*68 + p] = v.w;
    }
    __syncthreads();

    // phase 3: Yoff[l][p] = exp(acs[l]) * sum_n C[l,n] * prev[p,n]
    float y2[8][4];
#pragma unroll
    for (int i = 0; i < 8; i++)
#pragma unroll
        for (int j = 0; j < 4; j++) y2[i][j] = 0.f;
#pragma unroll 4
    for (int n = 0; n < 128; n++) {
        float a[8];
        *(float4*)(a)   = *(const float4*)&Ct[n*132 + ty*8];
        *(float4*)(a+4) = *(const float4*)&Ct[n*132 + ty*8 + 4];
        float4 pv = *(const float4*)&Xs[n*68 + tx*4];
#pragma unroll
        for (int i = 0; i < 8; i++) {
            y2[i][0] = fmaf(a[i], pv.x, y2[i][0]);
            y2[i][1] = fmaf(a[i], pv.y, y2[i][1]);
            y2[i][2] = fmaf(a[i], pv.z, y2[i][2]);
            y2[i][3] = fmaf(a[i], pv.w, y2[i][3]);
        }
    }
    float Dh = Dv[h];
#pragma unroll
    for (int i = 0; i < 8; i++) {
        int l = ty*8 + i;
        float el = __expf(sAcs[l]);
        float4 o;
        o.x = y[i][0] + el*y2[i][0] + xr[i][0]*Dh;
        o.y = y[i][1] + el*y2[i][1] + xr[i][1]*Dh;
        o.z = y[i][2] + el*y2[i][2] + xr[i][2]*Dh;
        o.w = y[i][3] + el*y2[i][3] + xr[i][3]*Dh;
        *(float4*)(g_y + (size_t)(rowBase + l)*DI + h*HD + tx*4) = o;
    }
}

// ---------------- gated rmsnorm: rmsnorm(y * silu(z)) * gw ----------------
__global__ void k_gnorm(const float* __restrict__ gw) {
    int m = blockIdx.x;
    const float* yr = g_y + (size_t)m*DI;
    const float* zr = g_zx + (size_t)m*DPROJ;
    float v[8];
    float s = 0.f;
#pragma unroll
    for (int i = 0; i < 8; i++) {
        int d = threadIdx.x + i*256;
        float z = zr[d];
        float val = yr[d] * (z / (1.f + __expf(-z)));
        v[i] = val; s += val*val;
    }
    __shared__ float sh[8];
#pragma unroll
    for (int o = 16; o > 0; o >>= 1) s += __shfl_xor_sync(0xffffffffu, s, o);
    if ((threadIdx.x & 31) == 0) sh[threadIdx.x >> 5] = s;
    __syncthreads();
    if (threadIdx.x < 8) {
        float t2 = sh[threadIdx.x];
#pragma unroll
        for (int o = 4; o > 0; o >>= 1) t2 += __shfl_xor_sync(0xffu, t2, o);
        if (threadIdx.x == 0) sh[0] = t2;
    }
    __syncthreads();
    float inv = rsqrtf(sh[0] * (1.f/DI) + 1e-5f);
#pragma unroll
    for (int i = 0; i < 8; i++) {
        int d = threadIdx.x + i*256;
        g_yn[(size_t)m*DI + d] = v[i] * inv * gw[d];
    }
}

// ---------------- host launcher ----------------
extern "C" void kernel_launch(void* const* d_in, const int* in_sizes, int n_in,
                              void* d_out, int out_size) {
    (void)in_sizes; (void)n_in; (void)out_size;
    const float* x         = (const float*)d_in[0];
    const float* norm_w    = (const float*)d_in[1];
    const float* out_w_blk = (const float*)d_in[2];
    const float* out_b_blk = (const float*)d_in[3];

    cudaFuncSetAttribute(k_y, cudaFuncAttributeMaxDynamicSharedMemorySize, YSMEM);

    void* p;
    cudaGetSymbolAddress(&p, g_xn);   float* xn   = (float*)p;
    cudaGetSymbolAddress(&p, g_zx);   float* zx   = (float*)p;
    cudaGetSymbolAddress(&p, g_yn);   float* yn   = (float*)p;
    cudaGetSymbolAddress(&p, g_ycat); float* ycat = (float*)p;

    k_rmsnorm_in<<<MTOT, 256>>>(x, norm_w);

    for (int dir = 0; dir < 2; dir++) {
        const float* in_w    = (const float*)d_in[4 + dir*8 + 0];
        const float* conv_w  = (const float*)d_in[4 + dir*8 + 1];
        const float* conv_b  = (const float*)d_in[4 + dir*8 + 2];
        const float* dt_bias = (const float*)d_in[4 + dir*8 + 3];
        const float* A_log   = (const float*)d_in[4 + dir*8 + 4];
        const float* Dv      = (const float*)d_in[4 + dir*8 + 5];
        const float* gnorm_w = (const float*)d_in[4 + dir*8 + 6];
        const float* out_w   = (const float*)d_in[4 + dir*8 + 7];

        // zxbcdt = xn_dir @ in_w^T   (4096 x 4384 x 1024)
        k_sgemm<<<dim3((DPROJ + 127)/128, MTOT/128), 256>>>(
            xn + (size_t)dir*MTOT*DM, in_w, zx, DPROJ, DM, DPROJ, 0, 0, nullptr, nullptr);
        k_dtacs<<<BATCHN*NH*NC, CHK>>>(dt_bias, A_log);
        k_conv<<<dim3(CONVCH/256, MTOT), 256>>>(conv_w, conv_b);
        k_states<<<BATCHN*NC*NH, 256>>>();
        k_scan<<<(BATCHN*NH*HD*DS)/256, 256>>>();
        k_y<<<BATCHN*NC*NH, 256, YSMEM>>>(Dv);
        k_gnorm<<<MTOT, 256>>>(gnorm_w);
        // out-proj into ycat half (backward dir writes rows time-flipped back)
        k_sgemm<<<dim3(DM/128, MTOT/128), 256>>>(
            yn, out_w, ycat, DM, DI, 2*DM, dir*DM, dir, nullptr, nullptr);
    }

    // final: out = x + ycat @ out_w_blk^T + out_b_blk
    k_sgemm<<<dim3(DM/128, MTOT/128), 256>>>(
        ycat, out_w_blk, (float*)d_out, DM, DI, DM, 0, 0, out_b_blk, x);
}

// round 6
// speedup vs baseline: 2.0203x; 2.0203x over previous
#include <cuda_runtime.h>
#include <cuda_bf16.h>
#include <math.h>
#include <stdint.h>

// ---------------- constants ----------------
#define BATCHN 2
#define SEQL   2048
#define DM     1024
#define DI     2048
#define DS     128
#define NH     32
#define HD     64
#define DPROJ  4384      // 2*DI + 2*DS + NH
#define CONVCH 2304      // DI + 2*DS
#define NC     16
#define CHK    128
#define MTOT   (BATCHN*SEQL)   // 4096

// GEMM tiling
#define BM 128
#define BN 128
#define BK 32
#define STR 40                     // smem row stride (elements); 80B -> conflict-free ldmatrix
#define STAGE_B (BM*STR*2)         // 10240 bytes per operand tile
#define GEMM_SMEM (4*STAGE_B)      // 40960 (A0,A1,B0,B1)
#define KP_IN  3072                // 3*1024
#define KP_OUT 6144                // 3*2048
#define NPAD_IN 4480               // 35 tiles
#define ASEG ((size_t)MTOT*KP_IN)

// ---------------- scratch ----------------
__device__ __align__(16) float g_zx[(size_t)MTOT*DPROJ];
__device__ __align__(16) float g_dt[MTOT*NH];
__device__ __align__(16) float g_acs[BATCHN*NH*NC*CHK];
__device__ __align__(16) float g_conv[(size_t)MTOT*CONVCH];
__device__ __align__(16) float g_states[(size_t)BATCHN*NC*NH*HD*DS];
__device__ __align__(16) float g_prev[(size_t)BATCHN*NC*NH*HD*DS];
__device__ __align__(16) float g_y[(size_t)MTOT*DI];

// packed bf16 split operands, plain row-major
__device__ __align__(16) __nv_bfloat16 g_Axn[(size_t)2*MTOT*KP_IN];   // [dir][4096][3072] = [hi|lo|hi]
__device__ __align__(16) __nv_bfloat16 g_Ayn[(size_t)MTOT*KP_OUT];    // [4096][6144]
__device__ __align__(16) __nv_bfloat16 g_Aycat[(size_t)MTOT*KP_OUT];  // [4096][6144]
__device__ __align__(16) __nv_bfloat16 g_Bw[(size_t)NPAD_IN*KP_IN];   // [hi|hi|lo], max size

// ---------------- PTX helpers (base-target legal: cp.async/ldmatrix/mma.sync) ----------------
__device__ __forceinline__ uint32_t smem_u32(const void* p) {
    uint32_t a;
    asm("{ .reg .u64 t; cvta.to.shared.u64 t, %1; cvt.u32.u64 %0, t; }" : "=r"(a) : "l"(p));
    return a;
}
#define CP16(dst, src) asm volatile("cp.async.cg.shared.global [%0], [%1], 16;" :: "r"(dst), "l"(src))
#define CP_COMMIT()    asm volatile("cp.async.commit_group;")
#define CP_WAIT0()     asm volatile("cp.async.wait_group 0;")
#define LDSM4(r0,r1,r2,r3,addr) \
    asm volatile("ldmatrix.sync.aligned.m8n8.x4.shared.b16 {%0,%1,%2,%3}, [%4];" \
        : "=r"(r0),"=r"(r1),"=r"(r2),"=r"(r3) : "r"(addr))
#define MMA16816(d, a, b) \
    asm volatile("mma.sync.aligned.m16n8k16.row.col.f32.bf16.bf16.f32 " \
        "{%0,%1,%2,%3}, {%4,%5,%6,%7}, {%8,%9}, {%0,%1,%2,%3};" \
        : "+f"((d)[0]),"+f"((d)[1]),"+f"((d)[2]),"+f"((d)[3]) \
        : "r"((a)[0]),"r"((a)[1]),"r"((a)[2]),"r"((a)[3]), "r"((b)[0]),"r"((b)[1]))

// ---------------- K0: input rmsnorm -> packed bf16 splits (both dirs) ----------------
__global__ void k_rmsnorm_in(const float* __restrict__ x, const float* __restrict__ w) {
    int m = blockIdx.x;
    int t = m & (SEQL - 1);
    int d0 = threadIdx.x << 2;
    float4 v = *(const float4*)(x + (size_t)m*DM + d0);
    float s = v.x*v.x + v.y*v.y + v.z*v.z + v.w*v.w;
    __shared__ float sh[8];
#pragma unroll
    for (int o = 16; o > 0; o >>= 1) s += __shfl_xor_sync(0xffffffffu, s, o);
    if ((threadIdx.x & 31) == 0) sh[threadIdx.x >> 5] = s;
    __syncthreads();
    if (threadIdx.x < 8) {
        float t2 = sh[threadIdx.x];
#pragma unroll
        for (int o = 4; o > 0; o >>= 1) t2 += __shfl_xor_sync(0xffu, t2, o);
        if (threadIdx.x == 0) sh[0] = t2;
    }
    __syncthreads();
    float inv = rsqrtf(sh[0] * (1.f/DM) + 1e-5f);
    float4 wv = *(const float4*)(w + d0);
    float o0 = v.x*inv*wv.x, o1 = v.y*inv*wv.y, o2 = v.z*inv*wv.z, o3 = v.w*inv*wv.w;
    __nv_bfloat162 h0, h1, l0, l1;
    h0.x = __float2bfloat16(o0); h0.y = __float2bfloat16(o1);
    h1.x = __float2bfloat16(o2); h1.y = __float2bfloat16(o3);
    l0.x = __float2bfloat16(o0 - __bfloat162float(h0.x));
    l0.y = __float2bfloat16(o1 - __bfloat162float(h0.y));
    l1.x = __float2bfloat16(o2 - __bfloat162float(h1.x));
    l1.y = __float2bfloat16(o3 - __bfloat162float(h1.y));
    int mf = m - t + (SEQL - 1 - t);
#pragma unroll
    for (int dir = 0; dir < 2; dir++) {
        int row = dir ? mf : m;
        __nv_bfloat16* b = g_Axn + (size_t)dir*ASEG + (size_t)row*KP_IN;
        *(__nv_bfloat162*)(b + d0)          = h0;
        *(__nv_bfloat162*)(b + d0 + 2)      = h1;
        *(__nv_bfloat162*)(b + 1024 + d0)   = l0;
        *(__nv_bfloat162*)(b + 1024 + d0+2) = l1;
        *(__nv_bfloat162*)(b + 2048 + d0)   = h0;
        *(__nv_bfloat162*)(b + 2048 + d0+2) = h1;
    }
}

// ---------------- weight split: W[N,K] fp32 -> row-major [Npad, 3K] = [hi|hi|lo] ----------------
__global__ void k_splitB(const float* __restrict__ W, __nv_bfloat16* __restrict__ O,
                         int N, int K) {
    int e = (blockIdx.x*256 + threadIdx.x) * 2;
    int row = e / K;
    int k = e - row*K;
    __nv_bfloat162 hv, lv;
    if (row < N) {
        float2 w = *(const float2*)(W + (size_t)row*K + k);
        hv.x = __float2bfloat16(w.x); hv.y = __float2bfloat16(w.y);
        lv.x = __float2bfloat16(w.x - __bfloat162float(hv.x));
        lv.y = __float2bfloat16(w.y - __bfloat162float(hv.y));
    } else {
        hv.x = __float2bfloat16(0.f); hv.y = hv.x; lv = hv;
    }
    __nv_bfloat16* o = O + (size_t)row*(3*K);
    *(__nv_bfloat162*)(o + k)       = hv;
    *(__nv_bfloat162*)(o + K + k)   = hv;
    *(__nv_bfloat162*)(o + 2*K + k) = lv;
}

// ---------------- mma.sync bf16 GEMM: C[M,N] = A[M,K']·B[N,K']^T ----------------
// splitOut=0: fp32 out (ldc/colOff/flip/bias/resid).  splitOut=1: packed [hi|lo|hi] bf16.
__global__ void __launch_bounds__(128) k_mma(
    const __nv_bfloat16* __restrict__ A, const __nv_bfloat16* __restrict__ Bp,
    void* __restrict__ Cout, int N, int Ktot, int ldc, int colOff, int flip,
    int splitOut, int K2tot, const float* __restrict__ bias, const float* __restrict__ resid)
{
    extern __shared__ __align__(16) char smraw[];
    uint32_t smA = smem_u32(smraw);          // A stages: +0, +STAGE_B
    uint32_t smB = smA + 2*STAGE_B;          // B stages: +0, +STAGE_B
    int tid = threadIdx.x, lane = tid & 31, wid = tid >> 5;
    int wm = wid & 1, wn = wid >> 1;         // 2x2 warps, warp tile 64x64
    int m0 = blockIdx.y << 7, n0 = blockIdx.x << 7;

    const __nv_bfloat16* Ab = A  + (size_t)m0*Ktot;
    const __nv_bfloat16* Bb = Bp + (size_t)n0*Ktot;

    float acc[4][8][4];
#pragma unroll
    for (int i = 0; i < 4; i++)
#pragma unroll
        for (int j = 0; j < 8; j++)
#pragma unroll
            for (int q = 0; q < 4; q++) acc[i][j][q] = 0.f;

    int ldrow = tid >> 2, ldcol = (tid & 3) * 8;   // 16B chunk coords

    // prologue: stage 0
    {
        const __nv_bfloat16* Ag = Ab; const __nv_bfloat16* Bg = Bb;
#pragma unroll
        for (int i = 0; i < 4; i++) {
            int row = ldrow + i*32;
            CP16(smA + row*(STR*2) + ldcol*2, Ag + (size_t)row*Ktot + ldcol);
            CP16(smB + row*(STR*2) + ldcol*2, Bg + (size_t)row*Ktot + ldcol);
        }
        CP_COMMIT();
    }

    int nk = Ktot / BK;
    // per-lane ldmatrix address components (bytes)
    int aoff = (wm*64 + (lane & 15))*(STR*2) + ((lane >> 4) << 4);
    int boff = (wn*64 + (lane & 7) + ((lane & 16) >> 1))*(STR*2) + ((lane & 8) << 1);

    for (int kt = 0; kt < nk; kt++) {
        int s = kt & 1;
        CP_WAIT0();
        __syncthreads();
        if (kt + 1 < nk) {
            const __nv_bfloat16* Ag = Ab + (size_t)(kt+1)*BK;
            const __nv_bfloat16* Bg = Bb + (size_t)(kt+1)*BK;
            uint32_t da = smA + (s^1)*STAGE_B, db = smB + (s^1)*STAGE_B;
#pragma unroll
            for (int i = 0; i < 4; i++) {
                int row = ldrow + i*32;
                CP16(da + row*(STR*2) + ldcol*2, Ag + (size_t)row*Ktot + ldcol);
                CP16(db + row*(STR*2) + ldcol*2, Bg + (size_t)row*Ktot + ldcol);
            }
            CP_COMMIT();
        }
        uint32_t sa = smA + s*STAGE_B + aoff;
        uint32_t sb = smB + s*STAGE_B + boff;
#pragma unroll
        for (int ks = 0; ks < 2; ks++) {
            uint32_t af[4][4], bf[8][2];
#pragma unroll
            for (int i = 0; i < 4; i++)
                LDSM4(af[i][0], af[i][1], af[i][2], af[i][3], sa + i*(16*STR*2) + ks*32);
#pragma unroll
            for (int j2 = 0; j2 < 4; j2++) {
                uint32_t r0, r1, r2, r3;
                LDSM4(r0, r1, r2, r3, sb + j2*(16*STR*2) + ks*32);
                bf[j2*2][0] = r0;   bf[j2*2][1] = r1;
                bf[j2*2+1][0] = r2; bf[j2*2+1][1] = r3;
            }
#pragma unroll
            for (int i = 0; i < 4; i++)
#pragma unroll
                for (int j = 0; j < 8; j++)
                    MMA16816(acc[i][j], af[i], bf[j]);
        }
        __syncthreads();
    }

    // epilogue
#pragma unroll
    for (int i = 0; i < 4; i++) {
        int r0 = m0 + wm*64 + i*16 + (lane >> 2);
#pragma unroll
        for (int half = 0; half < 2; half++) {
            int r = r0 + half*8;
            int orow = r;
            if (flip) { int tt = r & (SEQL-1); orow = r - tt + (SEQL-1-tt); }
#pragma unroll
            for (int j = 0; j < 8; j++) {
                int col = (blockIdx.x << 7) + wn*64 + j*8 + (lane & 3)*2;
                float v0 = acc[i][j][half*2], v1 = acc[i][j][half*2+1];
                if (splitOut) {
                    __nv_bfloat16* O = (__nv_bfloat16*)Cout + (size_t)orow*(3*K2tot);
                    int cg = colOff + col;
                    __nv_bfloat162 hv, lv;
                    hv.x = __float2bfloat16(v0); hv.y = __float2bfloat16(v1);
                    lv.x = __float2bfloat16(v0 - __bfloat162float(hv.x));
                    lv.y = __float2bfloat16(v1 - __bfloat162float(hv.y));
                    *(__nv_bfloat162*)(O + cg)           = hv;
                    *(__nv_bfloat162*)(O + K2tot + cg)   = lv;
                    *(__nv_bfloat162*)(O + 2*K2tot + cg) = hv;
                } else if (col < N) {
                    float* O = (float*)Cout + (size_t)orow*ldc + colOff + col;
                    if (bias)  { v0 += bias[col]; v1 += bias[col+1]; }
                    if (resid) { v0 += resid[(size_t)orow*ldc + col];
                                 v1 += resid[(size_t)orow*ldc + col + 1]; }
                    *(float2*)O = make_float2(v0, v1);
                }
            }
        }
    }
}

// ---------------- dt (softplus) + per-chunk cumsum of A*dt ----------------
__global__ void k_dtacs(const float* __restrict__ dt_bias, const float* __restrict__ A_log) {
    int bi = blockIdx.x;
    int h = bi & 31, c = (bi >> 5) & 15, b = bi >> 9;
    int l = threadIdx.x;
    int m = b*SEQL + c*CHK + l;
    float raw = g_zx[(size_t)m*DPROJ + (2*DI + 2*DS) + h] + dt_bias[h];
    float dt = fmaxf(raw, 0.f) + log1pf(expf(-fabsf(raw)));
    g_dt[m*NH + h] = dt;
    float Ah = -expf(A_log[h]);
    __shared__ float sv[CHK];
    float a = Ah * dt;
    sv[l] = a;
    __syncthreads();
#pragma unroll
    for (int off = 1; off < CHK; off <<= 1) {
        float u = (l >= off) ? sv[l - off] : 0.f;
        __syncthreads();
        a += u;
        sv[l] = a;
        __syncthreads();
    }
    g_acs[((b*NH + h)*NC + c)*CHK + l] = a;
}

// ---------------- causal depthwise conv (width 4) + silu ----------------
__global__ void k_conv(const float* __restrict__ cw, const float* __restrict__ cb) {
    int ch = blockIdx.x*256 + threadIdx.x;
    int m = blockIdx.y;
    int t = m & (SEQL - 1);
    float acc = cb[ch];
#pragma unroll
    for (int k = 0; k < 4; k++) {
        int tt = t + k - 3;
        if (tt >= 0) acc += g_zx[(size_t)(m + k - 3)*DPROJ + DI + ch] * cw[ch*4 + k];
    }
    float sg = 1.f / (1.f + __expf(-acc));
    g_conv[(size_t)m*CONVCH + ch] = acc * sg;
}

// ---------------- per-chunk states ----------------
__global__ void __launch_bounds__(256) k_states() {
    int bi = blockIdx.x;
    int h = bi & 31, c = (bi >> 5) & 15, b = bi >> 9;
    __shared__ __align__(16) float Bsh[32][132];
    __shared__ __align__(16) float Xd[32][68];
    int tid = threadIdx.x, tx = tid & 15, ty = tid >> 4;
    const float* acsr = g_acs + ((b*NH + h)*NC + c)*CHK;
    float alast = acsr[CHK - 1];
    int rowBase = b*SEQL + c*CHK;
    float acc[4][8];
#pragma unroll
    for (int i = 0; i < 4; i++)
#pragma unroll
        for (int j = 0; j < 8; j++) acc[i][j] = 0.f;

    for (int lt = 0; lt < CHK; lt += 32) {
#pragma unroll
        for (int i = 0; i < 4; i++) {
            int id = tid + i*256;
            int l = id >> 5, n4 = (id & 31) << 2;
            float4 v = *(const float4*)(g_conv + (size_t)(rowBase + lt + l)*CONVCH + DI + n4);
            *(float4*)&Bsh[l][n4] = v;
        }
#pragma unroll
        for (int i = 0; i < 2; i++) {
            int id = tid + i*256;
            int l = id >> 4, p4 = (id & 15) << 2;
            int row = rowBase + lt + l;
            float4 v = *(const float4*)(g_conv + (size_t)row*CONVCH + h*HD + p4);
            float f = g_dt[row*NH + h] * __expf(alast - acsr[lt + l]);
            v.x *= f; v.y *= f; v.z *= f; v.w *= f;
            *(float4*)&Xd[l][p4] = v;
        }
        __syncthreads();
#pragma unroll 8
        for (int l = 0; l < 32; l++) {
            float a[4], bb[8];
            *(float4*)a      = *(const float4*)&Xd[l][ty*4];
            *(float4*)(bb)   = *(const float4*)&Bsh[l][tx*8];
            *(float4*)(bb+4) = *(const float4*)&Bsh[l][tx*8+4];
#pragma unroll
            for (int i = 0; i < 4; i++)
#pragma unroll
                for (int j = 0; j < 8; j++) acc[i][j] = fmaf(a[i], bb[j], acc[i][j]);
        }
        __syncthreads();
    }
    size_t base = ((size_t)((b*NC + c)*NH + h)) * HD * DS;
#pragma unroll
    for (int i = 0; i < 4; i++) {
        int p = ty*4 + i;
#pragma unroll
        for (int j = 0; j < 8; j += 4) {
            float4 v = make_float4(acc[i][j], acc[i][j+1], acc[i][j+2], acc[i][j+3]);
            *(float4*)(g_states + base + (size_t)p*DS + tx*8 + j) = v;
        }
    }
}

// ---------------- sequential inter-chunk scan ----------------
__global__ void k_scan() {
    int idx = blockIdx.x*256 + threadIdx.x;
    int n = idx & 127;
    int p = (idx >> 7) & 63;
    int h = (idx >> 13) & 31;
    int b = idx >> 18;
    const float* acsb = g_acs + ((b*NH + h)*NC)*CHK;
    float s = 0.f;
#pragma unroll
    for (int c = 0; c < NC; c++) {
        size_t off = (((size_t)((b*NC + c)*NH + h))*HD + p)*DS + n;
        g_prev[off] = s;
        s = s * __expf(acsb[c*CHK + CHK - 1]) + g_states[off];
    }
}

// ---------------- per-(b,c,h) Y = diag + off + D-term ----------------
#define YSMEM ((128*132*2 + 128*68 + 256)*4)
__global__ void __launch_bounds__(256) k_y(const float* __restrict__ Dv) {
    extern __shared__ __align__(16) float sm[];
    float* Ct   = sm;
    float* Gt   = sm + 128*132;
    float* Xs   = Gt + 128*132;
    float* sAcs = Xs + 128*68;
    float* sDt  = sAcs + 128;

    int bi = blockIdx.x;
    int h = bi & 31, c = (bi >> 5) & 15, b = bi >> 9;
    int tid = threadIdx.x, tx = tid & 15, ty = tid >> 4;
    int rowBase = b*SEQL + c*CHK;
    const float* acsr = g_acs + ((b*NH + h)*NC + c)*CHK;
    if (tid < 128) { sAcs[tid] = acsr[tid]; sDt[tid] = g_dt[(rowBase + tid)*NH + h]; }

#pragma unroll
    for (int i = 0; i < 16; i++) {
        int id = tid + i*256;
        int l = id >> 5, n4 = (id & 31) << 2;
        const float* grow = g_conv + (size_t)(rowBase + l)*CONVCH;
        float4 vc = *(const float4*)(grow + DI + DS + n4);
        Ct[(n4+0)*132 + l] = vc.x; Ct[(n4+1)*132 + l] = vc.y;
        Ct[(n4+2)*132 + l] = vc.z; Ct[(n4+3)*132 + l] = vc.w;
        float4 vb = *(const float4*)(grow + DI + n4);
        Gt[(n4+0)*132 + l] = vb.x; Gt[(n4+1)*132 + l] = vb.y;
        Gt[(n4+2)*132 + l] = vb.z; Gt[(n4+3)*132 + l] = vb.w;
    }
#pragma unroll
    for (int i = 0; i < 8; i++) {
        int id = tid + i*256;
        int s = id >> 4, p4 = (id & 15) << 2;
        float4 v = *(const float4*)(g_conv + (size_t)(rowBase + s)*CONVCH + h*HD + p4);
        *(float4*)&Xs[s*68 + p4] = v;
    }
    __syncthreads();

    float g[8][8];
#pragma unroll
    for (int i = 0; i < 8; i++)
#pragma unroll
        for (int j = 0; j < 8; j++) g[i][j] = 0.f;
#pragma unroll 4
    for (int n = 0; n < 128; n++) {
        float a[8], bb[8];
        *(float4*)(a)    = *(const float4*)&Ct[n*132 + ty*8];
        *(float4*)(a+4)  = *(const float4*)&Ct[n*132 + ty*8 + 4];
        *(float4*)(bb)   = *(const float4*)&Gt[n*132 + tx*8];
        *(float4*)(bb+4) = *(const float4*)&Gt[n*132 + tx*8 + 4];
#pragma unroll
        for (int i = 0; i < 8; i++)
#pragma unroll
            for (int j = 0; j < 8; j++) g[i][j] = fmaf(a[i], bb[j], g[i][j]);
    }
#pragma unroll
    for (int i = 0; i < 8; i++) {
        int l = ty*8 + i; float al = sAcs[l];
#pragma unroll
        for (int j = 0; j < 8; j++) {
            int s = tx*8 + j;
            g[i][j] = (s <= l) ? g[i][j] * __expf(al - sAcs[s]) : 0.f;
        }
    }
    __syncthreads();
#pragma unroll
    for (int j = 0; j < 8; j++) {
        float4 v0 = make_float4(g[0][j], g[1][j], g[2][j], g[3][j]);
        float4 v1 = make_float4(g[4][j], g[5][j], g[6][j], g[7][j]);
        *(float4*)&Gt[(tx*8+j)*132 + ty*8]     = v0;
        *(float4*)&Gt[(tx*8+j)*132 + ty*8 + 4] = v1;
    }
    __syncthreads();

    float y[8][4];
#pragma unroll
    for (int i = 0; i < 8; i++)
#pragma unroll
        for (int j = 0; j < 4; j++) y[i][j] = 0.f;
#pragma unroll 4
    for (int s = 0; s < 128; s++) {
        float a[8];
        *(float4*)(a)   = *(const float4*)&Gt[s*132 + ty*8];
        *(float4*)(a+4) = *(const float4*)&Gt[s*132 + ty*8 + 4];
        float4 xv = *(const float4*)&Xs[s*68 + tx*4];
        float d = sDt[s];
        float bb[4] = {xv.x*d, xv.y*d, xv.z*d, xv.w*d};
#pragma unroll
        for (int i = 0; i < 8; i++)
#pragma unroll
            for (int j = 0; j < 4; j++) y[i][j] = fmaf(a[i], bb[j], y[i][j]);
    }
    float xr[8][4];
#pragma unroll
    for (int i = 0; i < 8; i++) {
        float4 v = *(const float4*)&Xs[(ty*8+i)*68 + tx*4];
        xr[i][0]=v.x; xr[i][1]=v.y; xr[i][2]=v.z; xr[i][3]=v.w;
    }
    __syncthreads();
    size_t pbase = ((size_t)((b*NC + c)*NH + h)) * HD * DS;
#pragma unroll
    for (int i = 0; i < 8; i++) {
        int id = tid + i*256;
        int p = id >> 5, n4 = (id & 31) << 2;
        float4 v = *(const float4*)(g_prev + pbase + (size_t)p*DS + n4);
        Xs[(n4+0)*68 + p] = v.x; Xs[(n4+1)*68 + p] = v.y;
        Xs[(n4+2)*68 + p] = v.z; Xs[(n4+3)*68 + p] = v.w;
    }
    __syncthreads();

    float y2[8][4];
#pragma unroll
    for (int i = 0; i < 8; i++)
#pragma unroll
        for (int j = 0; j < 4; j++) y2[i][j] = 0.f;
#pragma unroll 4
    for (int n = 0; n < 128; n++) {
        float a[8];
        *(float4*)(a)   = *(const float4*)&Ct[n*132 + ty*8];
        *(float4*)(a+4) = *(const float4*)&Ct[n*132 + ty*8 + 4];
        float4 pv = *(const float4*)&Xs[n*68 + tx*4];
#pragma unroll
        for (int i = 0; i < 8; i++) {
            y2[i][0] = fmaf(a[i], pv.x, y2[i][0]);
            y2[i][1] = fmaf(a[i], pv.y, y2[i][1]);
            y2[i][2] = fmaf(a[i], pv.z, y2[i][2]);
            y2[i][3] = fmaf(a[i], pv.w, y2[i][3]);
        }
    }
    float Dh = Dv[h];
#pragma unroll
    for (int i = 0; i < 8; i++) {
        int l = ty*8 + i;
        float el = __expf(sAcs[l]);
        float4 o;
        o.x = y[i][0] + el*y2[i][0] + xr[i][0]*Dh;
        o.y = y[i][1] + el*y2[i][1] + xr[i][1]*Dh;
        o.z = y[i][2] + el*y2[i][2] + xr[i][2]*Dh;
        o.w = y[i][3] + el*y2[i][3] + xr[i][3]*Dh;
        *(float4*)(g_y + (size_t)(rowBase + l)*DI + h*HD + tx*4) = o;
    }
}

// ---------------- gated rmsnorm -> packed bf16 splits (row-major) ----------------
__global__ void k_gnorm(const float* __restrict__ gw) {
    int m = blockIdx.x;
    int d0 = threadIdx.x << 3;
    const float* yr = g_y + (size_t)m*DI + d0;
    const float* zr = g_zx + (size_t)m*DPROJ + d0;
    float v[8];
    float s = 0.f;
#pragma unroll
    for (int q = 0; q < 2; q++) {
        float4 yv = *(const float4*)(yr + q*4);
        float4 zv = *(const float4*)(zr + q*4);
        v[q*4+0] = yv.x * (zv.x / (1.f + __expf(-zv.x)));
        v[q*4+1] = yv.y * (zv.y / (1.f + __expf(-zv.y)));
        v[q*4+2] = yv.z * (zv.z / (1.f + __expf(-zv.z)));
        v[q*4+3] = yv.w * (zv.w / (1.f + __expf(-zv.w)));
#pragma unroll
        for (int j = 0; j < 4; j++) s += v[q*4+j]*v[q*4+j];
    }
    __shared__ float sh[8];
#pragma unroll
    for (int o = 16; o > 0; o >>= 1) s += __shfl_xor_sync(0xffffffffu, s, o);
    if ((threadIdx.x & 31) == 0) sh[threadIdx.x >> 5] = s;
    __syncthreads();
    if (threadIdx.x < 8) {
        float t2 = sh[threadIdx.x];
#pragma unroll
        for (int o = 4; o > 0; o >>= 1) t2 += __shfl_xor_sync(0xffu, t2, o);
        if (threadIdx.x == 0) sh[0] = t2;
    }
    __syncthreads();
    float inv = rsqrtf(sh[0] * (1.f/DI) + 1e-5f);
    __nv_bfloat16* O = g_Ayn + (size_t)m*KP_OUT;
#pragma unroll
    for (int q = 0; q < 4; q++) {
        int d = d0 + q*2;
        float o0 = v[q*2]   * inv * gw[d];
        float o1 = v[q*2+1] * inv * gw[d+1];
        __nv_bfloat162 hv, lv;
        hv.x = __float2bfloat16(o0); hv.y = __float2bfloat16(o1);
        lv.x = __float2bfloat16(o0 - __bfloat162float(hv.x));
        lv.y = __float2bfloat16(o1 - __bfloat162float(hv.y));
        *(__nv_bfloat162*)(O + d)        = hv;
        *(__nv_bfloat162*)(O + 2048 + d) = lv;
        *(__nv_bfloat162*)(O + 4096 + d) = hv;
    }
}

// ---------------- host launcher ----------------
extern "C" void kernel_launch(void* const* d_in, const int* in_sizes, int n_in,
                              void* d_out, int out_size) {
    (void)in_sizes; (void)n_in; (void)out_size;
    const float* x         = (const float*)d_in[0];
    const float* norm_w    = (const float*)d_in[1];
    const float* out_w_blk = (const float*)d_in[2];
    const float* out_b_blk = (const float*)d_in[3];

    cudaFuncSetAttribute(k_y, cudaFuncAttributeMaxDynamicSharedMemorySize, YSMEM);

    void* p;
    cudaGetSymbolAddress(&p, g_Axn);   __nv_bfloat16* Axn   = (__nv_bfloat16*)p;
    cudaGetSymbolAddress(&p, g_Ayn);   __nv_bfloat16* Ayn   = (__nv_bfloat16*)p;
    cudaGetSymbolAddress(&p, g_Aycat); __nv_bfloat16* Aycat = (__nv_bfloat16*)p;
    cudaGetSymbolAddress(&p, g_Bw);    __nv_bfloat16* Bw    = (__nv_bfloat16*)p;
    cudaGetSymbolAddress(&p, g_zx);    float* zx = (float*)p;

    k_rmsnorm_in<<<MTOT, 256>>>(x, norm_w);

    for (int dir = 0; dir < 2; dir++) {
        const float* in_w    = (const float*)d_in[4 + dir*8 + 0];
        const float* conv_w  = (const float*)d_in[4 + dir*8 + 1];
        const float* conv_b  = (const float*)d_in[4 + dir*8 + 2];
        const float* dt_bias = (const float*)d_in[4 + dir*8 + 3];
        const float* A_log   = (const float*)d_in[4 + dir*8 + 4];
        const float* Dv      = (const float*)d_in[4 + dir*8 + 5];
        const float* gnorm_w = (const float*)d_in[4 + dir*8 + 6];
        const float* out_w   = (const float*)d_in[4 + dir*8 + 7];

        // split in_w -> Bw [4480][3072]
        k_splitB<<<(NPAD_IN*DM)/512, 256>>>(in_w, Bw, DPROJ, DM);
        // zx = xn_dir @ in_w^T  (fp32 out, N=4384)
        k_mma<<<dim3(NPAD_IN/128, MTOT/128), 128, GEMM_SMEM>>>(
            Axn + (size_t)dir*ASEG, Bw, zx, DPROJ, KP_IN, DPROJ, 0, 0, 0, 0, nullptr, nullptr);

        k_dtacs<<<BATCHN*NH*NC, CHK>>>(dt_bias, A_log);
        k_conv<<<dim3(CONVCH/256, MTOT), 256>>>(conv_w, conv_b);
        k_states<<<BATCHN*NC*NH, 256>>>();
        k_scan<<<(BATCHN*NH*HD*DS)/256, 256>>>();
        k_y<<<BATCHN*NC*NH, 256, YSMEM>>>(Dv);
        k_gnorm<<<MTOT, 256>>>(gnorm_w);

        // split out_w -> Bw [1024][6144]
        k_splitB<<<(DM*DI)/512, 256>>>(out_w, Bw, DM, DI);
        // ycat half (packed split output; backward dir rows un-flipped)
        k_mma<<<dim3(DM/128, MTOT/128), 128, GEMM_SMEM>>>(
            Ayn, Bw, Aycat, DM, KP_OUT, 0, dir*DM, dir, 1, DI, nullptr, nullptr);
    }

    // final: out = x + ycat @ out_w_blk^T + out_b_blk
    k_splitB<<<(DM*DI)/512, 256>>>(out_w_blk, Bw, DM, DI);
    k_mma<<<dim3(DM/128, MTOT/128), 128, GEMM_SMEM>>>(
        Aycat, Bw, (float*)d_out, DM, KP_OUT, DM, 0, 0, 0, 0, out_b_blk, x);
}